// round 16
// baseline (speedup 1.0000x reference)
#include <cuda_runtime.h>
#include <cuda_fp16.h>
#include <cstdint>
#include <cstddef>

#define NN 100000
#define EE 1600000
#define DD 64
#define GG 512

static constexpr int TILE  = 256;           // edges per tile
static constexpr int NTILE = EE / TILE;     // 6250 exact
static constexpr int GRID  = 296;           // 2 CTAs per SM
static constexpr int NTHR  = 512;           // 16 warps per CTA

// ---- smem layout (byte offsets) ----
static constexpr int OFF_SRC = 0;                      // 256 ints
static constexpr int OFF_DST = 1024;                   // 256 ints
static constexpr int OFF_BE  = 2048;                   // 64 f32
static constexpr int OFF_BM  = 2304;                   // 64 f32
static constexpr int OFF_A   = 4096;                   // 256 x 128B fp16 (A tile)
static constexpr int OFF_T   = OFF_A + 32768;          // 256 x 128B fp16 (T tile)
static constexpr int OFF_WE  = OFF_T + 32768;          // 64 x 128B fp16 (We^T)
static constexpr int OFF_WM  = OFF_WE + 8192;          // 64 x 128B fp16 (Wm^T)
static constexpr int SMEM_BYTES = OFF_WM + 8192;       // 86016

// ---------------- device scratch ----------------
__device__ float g_agg[(size_t)NN * DD];                 // 25.6 MB
__device__ float g_sum[GG], g_ss[GG], g_cnt[GG];
__device__ float g_mean[GG], g_rstd[GG];

// ---------------- helpers ----------------
// half2 silu via tanh.approx.f16x2: silu(x) = (x/2)*tanh(x/2) + (x/2)
__device__ __forceinline__ __half2 silu_h2(__half2 h) {
    const __half2 half_c = __floats2half2_rn(0.5f, 0.5f);
    __half2 hh = __hmul2(h, half_c);
    uint32_t ti, to;
    ti = *(uint32_t*)&hh;
    asm("tanh.approx.f16x2 %0, %1;" : "=r"(to) : "r"(ti));
    __half2 th = *(__half2*)&to;
    return __hfma2(hh, th, hh);
}
// XOR-swizzled offset for a 128B-row tile: row r, float4-chunk c4 (0..15)
__device__ __forceinline__ uint32_t a_off(int r, int c4) {
    return (uint32_t)r * 128u
         + (uint32_t)(((((c4 >> 1) ^ (r & 7))) << 4) + ((c4 & 1) << 3));
}
__device__ __forceinline__ uint32_t w_off(int n, int k) {
    return (uint32_t)n * 128u
         + (uint32_t)(((((k >> 3) ^ (n & 7))) << 4) + ((k & 7) << 1));
}
__device__ __forceinline__ uint32_t pack2h(float a, float b) {
    __half2 h = __floats2half2_rn(a, b);
    return *(uint32_t*)&h;
}

__device__ __forceinline__ void ldm4(uint32_t addr, uint32_t r[4]) {
    asm volatile("ldmatrix.sync.aligned.m8n8.x4.shared.b16 {%0,%1,%2,%3}, [%4];"
                 : "=r"(r[0]), "=r"(r[1]), "=r"(r[2]), "=r"(r[3]) : "r"(addr));
}
__device__ __forceinline__ void mma_f16(float* c, const uint32_t a[4],
                                        uint32_t b0, uint32_t b1) {
    asm volatile(
        "mma.sync.aligned.m16n8k16.row.col.f32.f16.f16.f32 "
        "{%0,%1,%2,%3}, {%4,%5,%6,%7}, {%8,%9}, {%0,%1,%2,%3};"
        : "+f"(c[0]), "+f"(c[1]), "+f"(c[2]), "+f"(c[3])
        : "r"(a[0]), "r"(a[1]), "r"(a[2]), "r"(a[3]), "r"(b0), "r"(b1));
}

// 256x64x64 GEMM, 16 warps: warp w owns rows 16w..16w+15; single-term fp16.
__device__ __forceinline__ void run_gemm(uint32_t aB, uint32_t wB,
                                         int w, int l, float acc[8][4]) {
    const int rowA = 16 * w + (l & 7) + (l & 8);
    const uint32_t aRow = (uint32_t)rowA * 128u;
    const int rA7 = rowA & 7;
    const int chAsel = (l >> 4) & 1;
    const int nB0 = (l & 7) + ((l & 16) >> 1);
    const int chBsel = (l >> 3) & 1;
#pragma unroll
    for (int ks = 0; ks < 4; ++ks) {
        const int chA = 2 * ks + chAsel;
        const uint32_t aOff = aRow + (uint32_t)((chA ^ rA7) << 4);
        uint32_t ah[4];
        ldm4(aB + aOff, ah);
        const int chB = 2 * ks + chBsel;
#pragma unroll
        for (int p = 0; p < 4; ++p) {
            const int nB = nB0 + 16 * p;
            const uint32_t bOff = (uint32_t)nB * 128u
                                + (uint32_t)((chB ^ (nB & 7)) << 4);
            uint32_t bh[4];
            ldm4(wB + bOff, bh);
            mma_f16(acc[2 * p],     ah, bh[0], bh[1]);
            mma_f16(acc[2 * p + 1], ah, bh[2], bh[3]);
        }
    }
}

// ---------------- no-op kernel (keeps the ncu -s slot on edge_kernel) ----------
__global__ void nop_kernel() {}

// ---------------- kernel 1: agg = (1+eps)*x ; zero per-graph stats ----------------
__global__ void init_kernel(const float* __restrict__ x, const float* __restrict__ eps2) {
    const float s = 1.0f + eps2[0];
    const float4* x4 = (const float4*)x;
    float4* a4 = (float4*)g_agg;
    const int total = NN * (DD / 4);
    for (int i = blockIdx.x * blockDim.x + threadIdx.x; i < total;
         i += gridDim.x * blockDim.x) {
        const float4 v = x4[i];
        a4[i] = make_float4(s * v.x, s * v.y, s * v.z, s * v.w);
    }
    if (blockIdx.x == 0) {
        for (int t = threadIdx.x; t < GG; t += blockDim.x) {
            g_sum[t] = 0.0f; g_ss[t] = 0.0f; g_cnt[t] = 0.0f;
        }
    }
}

// ---------------- kernel 2: persistent fp16-mma GINE conv (512 thr, 256 edges) --
__global__ void __launch_bounds__(NTHR, 2)
edge_kernel(const float* __restrict__ x, const int* __restrict__ eidx,
            const float* __restrict__ eattr,
            const float* __restrict__ We, const float* __restrict__ be,
            const float* __restrict__ Wm, const float* __restrict__ bm) {
    extern __shared__ char smem[];
    uint32_t sbase;
    asm("{ .reg .u64 t; cvta.to.shared.u64 t, %1; cvt.u32.u64 %0, t; }"
        : "=r"(sbase) : "l"(smem));

    const int tid = threadIdx.x;
    const int w = tid >> 5;              // 0..15
    const int l = tid & 31;
    const int c = l & 3;                 // fragment column sub-index

    int* s_src = (int*)(smem + OFF_SRC);
    int* s_dst = (int*)(smem + OFF_DST);
    float* sbe = (float*)(smem + OFF_BE);
    float* sbm = (float*)(smem + OFF_BM);

    const uint32_t aB  = sbase + OFF_A;
    const uint32_t tB  = sbase + OFF_T;
    const uint32_t weB = sbase + OFF_WE;
    const uint32_t wmB = sbase + OFF_WM;

    // ---- one-time: transpose weights into smem (fp16), stage biases ----
    for (int idx = tid; idx < 4096; idx += NTHR) {
        const int k = idx >> 6, n = idx & 63;
        const uint32_t o = w_off(n, k);
        *(__half*)(smem + OFF_WE + o) = __float2half_rn(We[idx]);  // We[k][n]
        *(__half*)(smem + OFF_WM + o) = __float2half_rn(Wm[idx]);
    }
    if (tid < 64)       sbe[tid] = be[tid];
    else if (tid < 128) sbm[tid - 64] = bm[tid - 64];
    __syncthreads();

    // fragment row base for this thread
    const int m0 = 16 * w + (l >> 2);    // second row is m0 + 8 (0..255)
    const int sw0 = (m0 & 7);            // swizzle key (same for m0 and m0+8)
    const __half2 zero_h2 = __floats2half2_rn(0.0f, 0.0f);

    // ---- prologue: prefetch tile0 eattr (packed fp16) + this thread's index ----
    int tile = blockIdx.x;
    uint2 pr[8];                         // packed fp16 pairs (16 regs)
    int idxn;
    {
        const float4* ep4 = (const float4*)eattr + (size_t)tile * TILE * 16;
#pragma unroll
        for (int q = 0; q < 8; ++q) {
            const float4 v = __ldcs(ep4 + tid + NTHR * q);
            pr[q] = make_uint2(pack2h(v.x, v.y), pack2h(v.z, v.w));
        }
        idxn = (tid < 256) ? eidx[tile * TILE + tid]
                           : eidx[EE + tile * TILE + (tid - 256)];
    }

    for (; tile < NTILE; tile += GRID) {
        // ---- stage indices + A tile (fp16, swizzled) from registers ----
        if (tid < 256) s_src[tid] = idxn;
        else           s_dst[tid - 256] = idxn;
#pragma unroll
        for (int q = 0; q < 8; ++q) {
            const int f = tid + NTHR * q;           // float4 index 0..4095
            *(uint2*)(smem + OFF_A + a_off(f >> 4, f & 15)) = pr[q];
        }
        __syncthreads();   // S1: A tile + indices visible

        // fragment-layout index fetch + x gather (overlaps GEMM1)
        const int src0 = s_src[m0], src1 = s_src[m0 + 8];
        const int dst0 = s_dst[m0], dst1 = s_dst[m0 + 8];
        float2 xv0[8], xv1[8];
        {
            const float2* xr0 = (const float2*)(x + (size_t)src0 * DD) + c;
            const float2* xr1 = (const float2*)(x + (size_t)src1 * DD) + c;
#pragma unroll
            for (int nt = 0; nt < 8; ++nt) {
                xv0[nt] = xr0[4 * nt];
                xv1[nt] = xr1[4 * nt];
            }
        }

        // ---- GEMM1: ea = edge_attr @ We + be ----
        float acc[8][4];
#pragma unroll
        for (int nt = 0; nt < 8; ++nt) {
            const float2 bv = *(const float2*)(sbe + 8 * nt + 2 * c);
            acc[nt][0] = bv.x; acc[nt][1] = bv.y;
            acc[nt][2] = bv.x; acc[nt][3] = bv.y;
        }
        run_gemm(aB, weB, w, l, acc);

        // ---- epilogue1 (half2): t = relu(x_src + silu(ea)) -> T tile ----
#pragma unroll
        for (int nt = 0; nt < 8; ++nt) {
            const __half2 s0 = silu_h2(__floats2half2_rn(acc[nt][0], acc[nt][1]));
            const __half2 s1 = silu_h2(__floats2half2_rn(acc[nt][2], acc[nt][3]));
            const __half2 x0 = __floats2half2_rn(xv0[nt].x, xv0[nt].y);
            const __half2 x1 = __floats2half2_rn(xv1[nt].x, xv1[nt].y);
            const __half2 t0 = __hmax2(__hadd2(x0, s0), zero_h2);
            const __half2 t1 = __hmax2(__hadd2(x1, s1), zero_h2);
            const uint32_t o0 = (uint32_t)m0 * 128u + (uint32_t)((nt ^ sw0) << 4) + 4u * c;
            const uint32_t o1 = o0 + 8u * 128u;   // row m0+8, same swizzle key
            *(uint32_t*)(smem + OFF_T + o0) = *(const uint32_t*)&t0;
            *(uint32_t*)(smem + OFF_T + o1) = *(const uint32_t*)&t1;
        }
        __syncthreads();   // S2: T tile visible

        // prefetch next tile (packed at load; hidden under GEMM2 + epilogue2)
        const int nt_tile = tile + GRID;
        if (nt_tile < NTILE) {
            const float4* ep4 = (const float4*)eattr + (size_t)nt_tile * TILE * 16;
#pragma unroll
            for (int q = 0; q < 8; ++q) {
                const float4 v = __ldcs(ep4 + tid + NTHR * q);
                pr[q] = make_uint2(pack2h(v.x, v.y), pack2h(v.z, v.w));
            }
            idxn = (tid < 256) ? eidx[nt_tile * TILE + tid]
                               : eidx[EE + nt_tile * TILE + (tid - 256)];
        }

        // ---- GEMM2: msg = t @ Wm + bm ----
#pragma unroll
        for (int nt = 0; nt < 8; ++nt) {
            const float2 bv = *(const float2*)(sbm + 8 * nt + 2 * c);
            acc[nt][0] = bv.x; acc[nt][1] = bv.y;
            acc[nt][2] = bv.x; acc[nt][3] = bv.y;
        }
        run_gemm(tB, wmB, w, l, acc);

        // ---- epilogue2 (half2 silu): scatter-add into agg[dst] ----
        {
            float* p0 = g_agg + (size_t)dst0 * DD + 2 * c;
            float* p1 = g_agg + (size_t)dst1 * DD + 2 * c;
#pragma unroll
            for (int nt = 0; nt < 8; ++nt) {
                const __half2 s0 = silu_h2(__floats2half2_rn(acc[nt][0], acc[nt][1]));
                const __half2 s1 = silu_h2(__floats2half2_rn(acc[nt][2], acc[nt][3]));
                const float2 m01 = __half22float2(s0);
                const float2 m23 = __half22float2(s1);
                asm volatile("red.global.add.v2.f32 [%0], {%1,%2};"
                             :: "l"(p0 + 8 * nt), "f"(m01.x), "f"(m01.y) : "memory");
                asm volatile("red.global.add.v2.f32 [%0], {%1,%2};"
                             :: "l"(p1 + 8 * nt), "f"(m23.x), "f"(m23.y) : "memory");
            }
        }
        // No tail barrier: next iteration's A/idx writes are ordered by S1-next,
        // and all smem reads of this tile completed before S2 / into registers.
    }
}

// ---------------- kernel 3: per-graph sum / sumsq / count ----------------
__global__ void stats_kernel(const int* __restrict__ n2g) {
    const int lane = threadIdx.x & 31;
    const int wid  = (blockIdx.x * blockDim.x + threadIdx.x) >> 5;
    const int nwarps = (gridDim.x * blockDim.x) >> 5;
    for (int n = wid; n < NN; n += nwarps) {
        const float2 v = *(const float2*)(g_agg + (size_t)n * DD + lane * 2);
        float s = v.x + v.y;
        float q = v.x * v.x + v.y * v.y;
#pragma unroll
        for (int o = 16; o; o >>= 1) {
            s += __shfl_xor_sync(0xffffffffu, s, o);
            q += __shfl_xor_sync(0xffffffffu, q, o);
        }
        if (lane == 0) {
            const int g = n2g[n];
            atomicAdd(&g_sum[g], s);
            atomicAdd(&g_ss[g], q);
            atomicAdd(&g_cnt[g], 1.0f);
        }
    }
}

// ---------------- kernel 4: per-graph mean / rstd ----------------
__global__ void finalize_kernel() {
    const int t = threadIdx.x;
    if (t < GG) {
        const float c = fmaxf(g_cnt[t] * (float)DD, 1.0f);
        const float m = g_sum[t] / c;
        const float var = g_ss[t] / c - m * m;
        g_mean[t] = m;
        g_rstd[t] = rsqrtf(var + 1e-5f);
    }
}

// ---------------- kernel 5: normalize + affine + residual + relu ----------------
__global__ void norm_kernel(const float* __restrict__ x, const int* __restrict__ n2g,
                            const float* __restrict__ gamma, const float* __restrict__ beta,
                            float* __restrict__ out) {
    const float4* x4 = (const float4*)x;
    const float4* a4 = (const float4*)g_agg;
    const float4* g4 = (const float4*)gamma;
    const float4* b4 = (const float4*)beta;
    float4* o4 = (float4*)out;
    const int total = NN * (DD / 4);
    for (int i = blockIdx.x * blockDim.x + threadIdx.x; i < total;
         i += gridDim.x * blockDim.x) {
        const int n = i >> 4, c = i & 15;
        const int g = n2g[n];
        const float m = g_mean[g], r = g_rstd[g];
        const float4 a = a4[i], xv = x4[i], gm = g4[c], bt = b4[c];
        float4 o;
        o.x = fmaxf(fmaf((a.x - m) * r, gm.x, bt.x) + xv.x, 0.0f);
        o.y = fmaxf(fmaf((a.y - m) * r, gm.y, bt.y) + xv.y, 0.0f);
        o.z = fmaxf(fmaf((a.z - m) * r, gm.z, bt.z) + xv.z, 0.0f);
        o.w = fmaxf(fmaf((a.w - m) * r, gm.w, bt.w) + xv.w, 0.0f);
        __stcs(o4 + i, o);   // streamed: out is never re-read
    }
}

// ---------------- launch ----------------
// Inputs: 0:x 1:edge_index 2:edge_attr 3:node2graph
//   4..10: conv1/norm1 (dead branch)  11:We2 12:be2 13:Wm2 14:bm2 15:eps2 16:gamma2 17:beta2
extern "C" void kernel_launch(void* const* d_in, const int* in_sizes, int n_in,
                              void* d_out, int out_size) {
    const float* x      = (const float*)d_in[0];
    const int*   eidx   = (const int*)d_in[1];
    const float* eattr  = (const float*)d_in[2];
    const int*   n2g    = (const int*)d_in[3];
    const float* We2    = (const float*)d_in[11];
    const float* be2    = (const float*)d_in[12];
    const float* Wm2    = (const float*)d_in[13];
    const float* bm2    = (const float*)d_in[14];
    const float* eps2   = (const float*)d_in[15];
    const float* gamma2 = (const float*)d_in[16];
    const float* beta2  = (const float*)d_in[17];
    float* out = (float*)d_out;

    cudaFuncSetAttribute(edge_kernel,
                         cudaFuncAttributeMaxDynamicSharedMemorySize, SMEM_BYTES);

    init_kernel<<<2048, 256>>>(x, eps2);
    // keep the ncu -s slot (sequence position 4) on edge_kernel
    nop_kernel<<<1, 32>>>();
    nop_kernel<<<1, 32>>>();
    edge_kernel<<<GRID, NTHR, SMEM_BYTES>>>(x, eidx, eattr, We2, be2, Wm2, bm2);
    stats_kernel<<<1024, 256>>>(n2g);
    finalize_kernel<<<1, 512>>>();
    norm_kernel<<<2048, 256>>>(x, n2g, gamma2, beta2, out);
}

// round 17
// speedup vs baseline: 1.2046x; 1.2046x over previous
#include <cuda_runtime.h>
#include <cuda_fp16.h>
#include <cstdint>
#include <cstddef>

#define NN 100000
#define EE 1600000
#define DD 64
#define GG 512

static constexpr int TILE  = 128;           // edges per tile
static constexpr int NTILE = EE / TILE;     // 12500 exact
static constexpr int GRID  = 296;           // 2 CTAs per SM
static constexpr int NTHR  = 256;

// ---- smem layout (byte offsets) ----
static constexpr int OFF_SRC = 0;                      // 128 ints
static constexpr int OFF_DST = 512;                    // 128 ints
static constexpr int OFF_BE  = 1024;                   // 64 f32
static constexpr int OFF_BM  = 1280;                   // 64 f32
static constexpr int OFF_A   = 2048;                   // 128 x 128B fp16 (A tile)
static constexpr int OFF_T   = OFF_A + 16384;          // 128 x 128B fp16 (T / msg tile)
static constexpr int OFF_WE  = OFF_T + 16384;          // 64 x 128B fp16 (We^T)
static constexpr int OFF_WM  = OFF_WE + 8192;          // 64 x 128B fp16 (Wm^T)
static constexpr int SMEM_BYTES = OFF_WM + 8192;       // 51200

// ---------------- device scratch ----------------
__device__ float g_agg[(size_t)NN * DD];                 // 25.6 MB
__device__ float g_sum[GG], g_ss[GG], g_cnt[GG];
__device__ float g_mean[GG], g_rstd[GG];

// ---------------- helpers ----------------
// half2 silu via tanh.approx.f16x2: silu(x) = (x/2)*tanh(x/2) + (x/2)
__device__ __forceinline__ __half2 silu_h2(__half2 h) {
    const __half2 half_c = __floats2half2_rn(0.5f, 0.5f);
    __half2 hh = __hmul2(h, half_c);
    uint32_t ti, to;
    ti = *(uint32_t*)&hh;
    asm("tanh.approx.f16x2 %0, %1;" : "=r"(to) : "r"(ti));
    __half2 th = *(__half2*)&to;
    return __hfma2(hh, th, hh);
}
// XOR-swizzled offset for a 128B-row tile: row r, float4-chunk c4 (0..15)
__device__ __forceinline__ uint32_t a_off(int r, int c4) {
    return (uint32_t)r * 128u
         + (uint32_t)(((((c4 >> 1) ^ (r & 7))) << 4) + ((c4 & 1) << 3));
}
__device__ __forceinline__ uint32_t w_off(int n, int k) {
    return (uint32_t)n * 128u
         + (uint32_t)(((((k >> 3) ^ (n & 7))) << 4) + ((k & 7) << 1));
}
__device__ __forceinline__ uint32_t pack2h(float a, float b) {
    __half2 h = __floats2half2_rn(a, b);
    return *(uint32_t*)&h;
}

__device__ __forceinline__ void ldm4(uint32_t addr, uint32_t r[4]) {
    asm volatile("ldmatrix.sync.aligned.m8n8.x4.shared.b16 {%0,%1,%2,%3}, [%4];"
                 : "=r"(r[0]), "=r"(r[1]), "=r"(r[2]), "=r"(r[3]) : "r"(addr));
}
__device__ __forceinline__ void mma_f16(float* c, const uint32_t a[4],
                                        uint32_t b0, uint32_t b1) {
    asm volatile(
        "mma.sync.aligned.m16n8k16.row.col.f32.f16.f16.f32 "
        "{%0,%1,%2,%3}, {%4,%5,%6,%7}, {%8,%9}, {%0,%1,%2,%3};"
        : "+f"(c[0]), "+f"(c[1]), "+f"(c[2]), "+f"(c[3])
        : "r"(a[0]), "r"(a[1]), "r"(a[2]), "r"(a[3]), "r"(b0), "r"(b1));
}

// ---------------- no-op kernel (keeps the ncu -s slot on edge_kernel) ----------
__global__ void nop_kernel() {}

// ---------------- kernel 1: agg = (1+eps)*x ; zero per-graph stats ----------------
__global__ void init_kernel(const float* __restrict__ x, const float* __restrict__ eps2) {
    const float s = 1.0f + eps2[0];
    const float4* x4 = (const float4*)x;
    float4* a4 = (float4*)g_agg;
    const int total = NN * (DD / 4);
    for (int i = blockIdx.x * blockDim.x + threadIdx.x; i < total;
         i += gridDim.x * blockDim.x) {
        const float4 v = x4[i];
        a4[i] = make_float4(s * v.x, s * v.y, s * v.z, s * v.w);
    }
    if (blockIdx.x == 0) {
        for (int t = threadIdx.x; t < GG; t += blockDim.x) {
            g_sum[t] = 0.0f; g_ss[t] = 0.0f; g_cnt[t] = 0.0f;
        }
    }
}

// ---------------- kernel 2: persistent fp16-mma GINE conv --------------------
// N-half warp split: warp (wr = w&3, h = w>>2) owns rows 32wr..+31, cols 32h..+31.
// GEMM2's weight (Wm) fragments are preloaded into registers once per kernel.
// Scatter goes through the T tile and is issued as row-coalesced red.v2.
__global__ void __launch_bounds__(NTHR, 2)
edge_kernel(const float* __restrict__ x, const int* __restrict__ eidx,
            const float* __restrict__ eattr,
            const float* __restrict__ We, const float* __restrict__ be,
            const float* __restrict__ Wm, const float* __restrict__ bm) {
    extern __shared__ char smem[];
    uint32_t sbase;
    asm("{ .reg .u64 t; cvta.to.shared.u64 t, %1; cvt.u32.u64 %0, t; }"
        : "=r"(sbase) : "l"(smem));

    const int tid = threadIdx.x;
    const int w = tid >> 5;
    const int l = tid & 31;
    const int wr = w & 3;                // row block (32 rows)
    const int h  = w >> 2;               // column half (32 cols)
    const int c  = l & 3;                // fragment column sub-index

    int* s_src = (int*)(smem + OFF_SRC);
    int* s_dst = (int*)(smem + OFF_DST);
    float* sbe = (float*)(smem + OFF_BE);
    float* sbm = (float*)(smem + OFF_BM);

    const uint32_t aB  = sbase + OFF_A;
    const uint32_t tB  = sbase + OFF_T;
    const uint32_t weB = sbase + OFF_WE;
    const uint32_t wmB = sbase + OFF_WM;

    // ---- one-time: transpose weights into smem (fp16), stage biases ----
    for (int idx = tid; idx < 4096; idx += NTHR) {
        const int k = idx >> 6, n = idx & 63;
        const uint32_t o = w_off(n, k);
        *(__half*)(smem + OFF_WE + o) = __float2half_rn(We[idx]);  // We[k][n]
        *(__half*)(smem + OFF_WM + o) = __float2half_rn(Wm[idx]);
    }
    if (tid < 64)       sbe[tid] = be[tid];
    else if (tid < 128) sbm[tid - 64] = bm[tid - 64];
    __syncthreads();

    // ---- preload Wm fragments for this warp's column half (held all kernel) ----
    uint32_t wmr[4][2][4];               // [ks][q][frag] = 32 regs
#pragma unroll
    for (int ks = 0; ks < 4; ++ks) {
        const int chB = 2 * ks + ((l >> 3) & 1);
#pragma unroll
        for (int q = 0; q < 2; ++q) {
            const int nB = 32 * h + 16 * q + (l & 7) + ((l & 16) >> 1);
            const uint32_t bOff = (uint32_t)nB * 128u
                                + (uint32_t)((chB ^ (nB & 7)) << 4);
            ldm4(wmB + bOff, wmr[ks][q]);
        }
    }

    const int lr = l >> 2;               // 0..7 row sub-index
    const __half2 zero_h2 = __floats2half2_rn(0.0f, 0.0f);

    // ---- prologue: prefetch tile0 eattr (packed fp16) + this thread's index ----
    int tile = blockIdx.x;
    uint2 pr[8];
    int idxn;
    {
        const float4* ep4 = (const float4*)eattr + (size_t)tile * TILE * 16;
#pragma unroll
        for (int q = 0; q < 8; ++q) {
            const float4 v = __ldcs(ep4 + tid + NTHR * q);
            pr[q] = make_uint2(pack2h(v.x, v.y), pack2h(v.z, v.w));
        }
        idxn = (tid < 128) ? eidx[tile * TILE + tid]
                           : eidx[EE + tile * TILE + (tid - 128)];
    }

    for (; tile < NTILE; tile += GRID) {
        // ---- stage indices + A tile (fp16, swizzled) from registers ----
        if (tid < 128) s_src[tid] = idxn;
        else           s_dst[tid - 128] = idxn;
#pragma unroll
        for (int q = 0; q < 8; ++q) {
            const int f = tid + NTHR * q;           // float4 index 0..2047
            *(uint2*)(smem + OFF_A + a_off(f >> 4, f & 15)) = pr[q];
        }
        __syncthreads();   // S1: A tile + indices visible

        // ---- GEMM1: ea = edge_attr @ We + be (A smem, B smem) ----
        float acc[2][4][4];
#pragma unroll
        for (int mt = 0; mt < 2; ++mt)
#pragma unroll
            for (int nq = 0; nq < 4; ++nq) {
                const float2 bv = *(const float2*)(sbe + 32 * h + 8 * nq + 2 * c);
                acc[mt][nq][0] = bv.x; acc[mt][nq][1] = bv.y;
                acc[mt][nq][2] = bv.x; acc[mt][nq][3] = bv.y;
            }
        {
            const int rowA0 = 32 * wr + (l & 7) + (l & 8);
            const int rA7 = rowA0 & 7;
#pragma unroll
            for (int ks = 0; ks < 4; ++ks) {
                const int chA = 2 * ks + ((l >> 4) & 1);
                uint32_t a0[4], a1[4];
                const uint32_t aoff = (uint32_t)((chA ^ rA7) << 4);
                ldm4(aB + (uint32_t)rowA0 * 128u + aoff, a0);
                ldm4(aB + (uint32_t)(rowA0 + 16) * 128u + aoff, a1);
                const int chB = 2 * ks + ((l >> 3) & 1);
#pragma unroll
                for (int q = 0; q < 2; ++q) {
                    const int nB = 32 * h + 16 * q + (l & 7) + ((l & 16) >> 1);
                    const uint32_t bOff = (uint32_t)nB * 128u
                                        + (uint32_t)((chB ^ (nB & 7)) << 4);
                    uint32_t bh[4];
                    ldm4(weB + bOff, bh);
                    mma_f16(acc[0][2 * q],     a0, bh[0], bh[1]);
                    mma_f16(acc[0][2 * q + 1], a0, bh[2], bh[3]);
                    mma_f16(acc[1][2 * q],     a1, bh[0], bh[1]);
                    mma_f16(acc[1][2 * q + 1], a1, bh[2], bh[3]);
                }
            }
        }

        // ---- epilogue1: t = relu(x_src + silu(ea)) -> T tile (per 16-row half) --
#pragma unroll
        for (int mt = 0; mt < 2; ++mt) {
            const int r0 = 32 * wr + 16 * mt + lr;      // second row r0 + 8
            const int src0 = s_src[r0], src1 = s_src[r0 + 8];
            const float2* xr0 = (const float2*)(x + (size_t)src0 * DD) + 16 * h + c;
            const float2* xr1 = (const float2*)(x + (size_t)src1 * DD) + 16 * h + c;
            const uint32_t ob0 = (uint32_t)r0 * 128u + 4u * c;
            const int swk = r0 & 7;                      // same for r0+8
#pragma unroll
            for (int nq = 0; nq < 4; ++nq) {
                const float2 xv0 = xr0[4 * nq];
                const float2 xv1 = xr1[4 * nq];
                const __half2 s0 = silu_h2(__floats2half2_rn(acc[mt][nq][0], acc[mt][nq][1]));
                const __half2 s1 = silu_h2(__floats2half2_rn(acc[mt][nq][2], acc[mt][nq][3]));
                const __half2 t0 = __hmax2(__hadd2(__floats2half2_rn(xv0.x, xv0.y), s0), zero_h2);
                const __half2 t1 = __hmax2(__hadd2(__floats2half2_rn(xv1.x, xv1.y), s1), zero_h2);
                const uint32_t chs = (uint32_t)(((4 * h + nq) ^ swk) << 4);
                *(uint32_t*)(smem + OFF_T + ob0 + chs) = *(const uint32_t*)&t0;
                *(uint32_t*)(smem + OFF_T + ob0 + 8u * 128u + chs) = *(const uint32_t*)&t1;
            }
        }
        __syncthreads();   // S2: T tile visible

        // prefetch next tile (packed at load; hidden under GEMM2) ----
        const int nt_tile = tile + GRID;
        if (nt_tile < NTILE) {
            const float4* ep4 = (const float4*)eattr + (size_t)nt_tile * TILE * 16;
#pragma unroll
            for (int q = 0; q < 8; ++q) {
                const float4 v = __ldcs(ep4 + tid + NTHR * q);
                pr[q] = make_uint2(pack2h(v.x, v.y), pack2h(v.z, v.w));
            }
            idxn = (tid < 128) ? eidx[nt_tile * TILE + tid]
                               : eidx[EE + nt_tile * TILE + (tid - 128)];
        }

        // ---- GEMM2: msg = t @ Wm + bm (A smem, B in registers) ----
#pragma unroll
        for (int mt = 0; mt < 2; ++mt)
#pragma unroll
            for (int nq = 0; nq < 4; ++nq) {
                const float2 bv = *(const float2*)(sbm + 32 * h + 8 * nq + 2 * c);
                acc[mt][nq][0] = bv.x; acc[mt][nq][1] = bv.y;
                acc[mt][nq][2] = bv.x; acc[mt][nq][3] = bv.y;
            }
        {
            const int rowA0 = 32 * wr + (l & 7) + (l & 8);
            const int rA7 = rowA0 & 7;
#pragma unroll
            for (int ks = 0; ks < 4; ++ks) {
                const int chA = 2 * ks + ((l >> 4) & 1);
                uint32_t a0[4], a1[4];
                const uint32_t aoff = (uint32_t)((chA ^ rA7) << 4);
                ldm4(tB + (uint32_t)rowA0 * 128u + aoff, a0);
                ldm4(tB + (uint32_t)(rowA0 + 16) * 128u + aoff, a1);
#pragma unroll
                for (int q = 0; q < 2; ++q) {
                    mma_f16(acc[0][2 * q],     a0, wmr[ks][q][0], wmr[ks][q][1]);
                    mma_f16(acc[0][2 * q + 1], a0, wmr[ks][q][2], wmr[ks][q][3]);
                    mma_f16(acc[1][2 * q],     a1, wmr[ks][q][0], wmr[ks][q][1]);
                    mma_f16(acc[1][2 * q + 1], a1, wmr[ks][q][2], wmr[ks][q][3]);
                }
            }
        }
        __syncthreads();   // S3: all T reads (GEMM2) done before msg overwrites T

        // ---- write msg (half2) into T tile, fragment layout ----
#pragma unroll
        for (int mt = 0; mt < 2; ++mt) {
            const int r0 = 32 * wr + 16 * mt + lr;
            const uint32_t ob0 = (uint32_t)r0 * 128u + 4u * c;
            const int swk = r0 & 7;
#pragma unroll
            for (int nq = 0; nq < 4; ++nq) {
                const __half2 s0 = silu_h2(__floats2half2_rn(acc[mt][nq][0], acc[mt][nq][1]));
                const __half2 s1 = silu_h2(__floats2half2_rn(acc[mt][nq][2], acc[mt][nq][3]));
                const uint32_t chs = (uint32_t)(((4 * h + nq) ^ swk) << 4);
                *(uint32_t*)(smem + OFF_T + ob0 + chs) = *(const uint32_t*)&s0;
                *(uint32_t*)(smem + OFF_T + ob0 + 8u * 128u + chs) = *(const uint32_t*)&s1;
            }
        }
        __syncthreads();   // S4: msg tile complete

        // ---- row-coalesced scatter: warp w reduces rows 16w..16w+15 ----
        {
            const uint32_t lsw = (uint32_t)(l >> 2);
#pragma unroll
            for (int rr = 0; rr < 16; ++rr) {
                const int r = 16 * w + rr;
                const int dst = s_dst[r];
                const uint32_t o = (uint32_t)r * 128u
                                 + (uint32_t)(((lsw ^ (uint32_t)(r & 7)) << 4)) + 4u * (l & 3);
                const uint32_t pk = *(const uint32_t*)(smem + OFF_T + o);
                const __half2 hv = *(const __half2*)&pk;
                const float2 mv = __half22float2(hv);
                float* p = g_agg + (size_t)dst * DD + 2 * l;
                asm volatile("red.global.add.v2.f32 [%0], {%1,%2};"
                             :: "l"(p), "f"(mv.x), "f"(mv.y) : "memory");
            }
        }
        __syncthreads();   // S5: T/s_dst reads done before next tile's staging
    }
}

// ---------------- kernel 3: per-graph sum / sumsq / count ----------------
__global__ void stats_kernel(const int* __restrict__ n2g) {
    const int lane = threadIdx.x & 31;
    const int wid  = (blockIdx.x * blockDim.x + threadIdx.x) >> 5;
    const int nwarps = (gridDim.x * blockDim.x) >> 5;
    for (int n = wid; n < NN; n += nwarps) {
        const float2 v = *(const float2*)(g_agg + (size_t)n * DD + lane * 2);
        float s = v.x + v.y;
        float q = v.x * v.x + v.y * v.y;
#pragma unroll
        for (int o = 16; o; o >>= 1) {
            s += __shfl_xor_sync(0xffffffffu, s, o);
            q += __shfl_xor_sync(0xffffffffu, q, o);
        }
        if (lane == 0) {
            const int g = n2g[n];
            atomicAdd(&g_sum[g], s);
            atomicAdd(&g_ss[g], q);
            atomicAdd(&g_cnt[g], 1.0f);
        }
    }
}

// ---------------- kernel 4: per-graph mean / rstd ----------------
__global__ void finalize_kernel() {
    const int t = threadIdx.x;
    if (t < GG) {
        const float c = fmaxf(g_cnt[t] * (float)DD, 1.0f);
        const float m = g_sum[t] / c;
        const float var = g_ss[t] / c - m * m;
        g_mean[t] = m;
        g_rstd[t] = rsqrtf(var + 1e-5f);
    }
}

// ---------------- kernel 5: normalize + affine + residual + relu ----------------
__global__ void norm_kernel(const float* __restrict__ x, const int* __restrict__ n2g,
                            const float* __restrict__ gamma, const float* __restrict__ beta,
                            float* __restrict__ out) {
    const float4* x4 = (const float4*)x;
    const float4* a4 = (const float4*)g_agg;
    const float4* g4 = (const float4*)gamma;
    const float4* b4 = (const float4*)beta;
    float4* o4 = (float4*)out;
    const int total = NN * (DD / 4);
    for (int i = blockIdx.x * blockDim.x + threadIdx.x; i < total;
         i += gridDim.x * blockDim.x) {
        const int n = i >> 4, c = i & 15;
        const int g = n2g[n];
        const float m = g_mean[g], r = g_rstd[g];
        const float4 a = a4[i], xv = x4[i], gm = g4[c], bt = b4[c];
        float4 o;
        o.x = fmaxf(fmaf((a.x - m) * r, gm.x, bt.x) + xv.x, 0.0f);
        o.y = fmaxf(fmaf((a.y - m) * r, gm.y, bt.y) + xv.y, 0.0f);
        o.z = fmaxf(fmaf((a.z - m) * r, gm.z, bt.z) + xv.z, 0.0f);
        o.w = fmaxf(fmaf((a.w - m) * r, gm.w, bt.w) + xv.w, 0.0f);
        __stcs(o4 + i, o);   // streamed: out is never re-read
    }
}

// ---------------- launch ----------------
// Inputs: 0:x 1:edge_index 2:edge_attr 3:node2graph
//   4..10: conv1/norm1 (dead branch)  11:We2 12:be2 13:Wm2 14:bm2 15:eps2 16:gamma2 17:beta2
extern "C" void kernel_launch(void* const* d_in, const int* in_sizes, int n_in,
                              void* d_out, int out_size) {
    const float* x      = (const float*)d_in[0];
    const int*   eidx   = (const int*)d_in[1];
    const float* eattr  = (const float*)d_in[2];
    const int*   n2g    = (const int*)d_in[3];
    const float* We2    = (const float*)d_in[11];
    const float* be2    = (const float*)d_in[12];
    const float* Wm2    = (const float*)d_in[13];
    const float* bm2    = (const float*)d_in[14];
    const float* eps2   = (const float*)d_in[15];
    const float* gamma2 = (const float*)d_in[16];
    const float* beta2  = (const float*)d_in[17];
    float* out = (float*)d_out;

    cudaFuncSetAttribute(edge_kernel,
                         cudaFuncAttributeMaxDynamicSharedMemorySize, SMEM_BYTES);

    init_kernel<<<2048, 256>>>(x, eps2);
    // keep the ncu -s slot (sequence position 4) on edge_kernel
    nop_kernel<<<1, 32>>>();
    nop_kernel<<<1, 32>>>();
    edge_kernel<<<GRID, NTHR, SMEM_BYTES>>>(x, eidx, eattr, We2, be2, Wm2, bm2);
    stats_kernel<<<1024, 256>>>(n2g);
    finalize_kernel<<<1, 512>>>();
    norm_kernel<<<2048, 256>>>(x, n2g, gamma2, beta2, out);
}